// round 14
// baseline (speedup 1.0000x reference)
#include <cuda_runtime.h>
#include <math.h>

#define B    8
#define S    256
#define H    768
#define P    256
#define NE   20000
#define NT   100000
#define NR   200
#define HOPS 3

// ---------------- scratch (device globals) ----------------
__device__ float g_wvp[H];
__device__ float g_U[B * H];                 // unnormalized D (atomic acc)
__device__ float g_T[B];                     // softmax denominator per b
__device__ float g_Rlog[B * HOPS * NR];
__device__ float g_Clog[B * HOPS * 2];
__device__ float g_R[B * HOPS * NR];
__device__ float g_CS[B * HOPS * 2];
__device__ float g_LD[B * H];
__device__ float g_walkraw[B * HOPS * NE];   // RAW chained segment sums
__device__ float g_scores[B * NE];
__device__ float g_sums[B * HOPS];
__device__ float g_mx[B * HOPS];
__device__ float g_esum[B * HOPS];
__device__ float g_ebuf[B * HOPS * NE];
__device__ int   g_cnt[B];                   // last-block counters for rsm

// ---------------- helpers ----------------
__device__ __forceinline__ float warpSum(float v) {
    #pragma unroll
    for (int o = 16; o; o >>= 1) v += __shfl_xor_sync(0xffffffffu, v, o);
    return v;
}
__device__ __forceinline__ float warpMax(float v) {
    #pragma unroll
    for (int o = 16; o; o >>= 1) v = fmaxf(v, __shfl_xor_sync(0xffffffffu, v, o));
    return v;
}
__device__ __forceinline__ void atomicMaxF(float* addr, float val) {
    int old = __float_as_int(*addr);
    while (__int_as_float(old) < val) {
        int assumed = old;
        old = atomicCAS((int*)addr, assumed, __float_as_int(val));
        if (old == assumed) break;
    }
}

// ---------------- kernels ----------------

// zero atomic-accumulated scratch; first 768 warps compute wvp = W_v @ W_p
__global__ void k_init(const float* __restrict__ Wv, const float* __restrict__ Wp) {
    int idx = blockIdx.x * blockDim.x + threadIdx.x;          // 1875*256
    if (idx < B * HOPS * NE) g_walkraw[idx] = 0.f;
    if (idx < B * H) { g_U[idx] = 0.f; g_LD[idx] = 0.f; }
    if (idx < B * HOPS * NR) g_Rlog[idx] = 0.f;
    if (idx < B * HOPS * 2) g_Clog[idx] = 0.f;
    if (idx < B * HOPS) { g_sums[idx] = 0.f; g_esum[idx] = 0.f; g_mx[idx] = -1e30f; }
    if (idx < B) { g_T[idx] = 0.f; g_cnt[idx] = 0; }
    int warp = idx >> 5;
    int lane = threadIdx.x & 31;
    if (warp < H) {
        float acc = 0.f;
        #pragma unroll
        for (int p = lane; p < P; p += 32) acc += Wv[warp * P + p] * Wp[p];
        acc = warpSum(acc);
        if (lane == 0) g_wvp[warp] = acc;
    }
}

// single-pass: block holds 8 lhs rows in REGISTERS, computes logits + exp
// (no max-subtraction: softmax shift-invariant, logits ~ N(0,1)),
// accumulates U[b,h] += e*mask*x and T[b] += e. grid (32, B), 192 threads.
__global__ void k_D(const float* __restrict__ lhs, const float* __restrict__ mask) {
    int sc = blockIdx.x, b = blockIdx.y;
    int tid = threadIdx.x;                 // 192 = 6 warps
    int lane = tid & 31, wid = tid >> 5;
    __shared__ float red[8][6];
    __shared__ float sp[8];

    float4 w = ((const float4*)g_wvp)[tid];
    int s0 = sc * 8;
    const float4* base = (const float4*)(lhs + ((size_t)(b * S + s0)) * H) + tid;
    float4 v[8];
    float part[8];
    #pragma unroll
    for (int s = 0; s < 8; s++) {
        v[s] = base[(size_t)s * (H / 4)];
        part[s] = v[s].x * w.x + v[s].y * w.y + v[s].z * w.z + v[s].w * w.w;
    }
    #pragma unroll
    for (int s = 0; s < 8; s++) {
        float r = warpSum(part[s]);
        if (lane == 0) red[s][wid] = r;
    }
    __syncthreads();
    if (tid < 8) {
        float l = red[tid][0] + red[tid][1] + red[tid][2]
                + red[tid][3] + red[tid][4] + red[tid][5];
        float e = expf(l);
        sp[tid] = e * mask[b * S + s0 + tid];
        red[tid][0] = e;
    }
    __syncthreads();
    if (tid == 0) {
        float t = 0.f;
        #pragma unroll
        for (int s = 0; s < 8; s++) t += red[s][0];
        atomicAdd(&g_T[b], t);
    }
    float4 acc = make_float4(0.f, 0.f, 0.f, 0.f);
    #pragma unroll
    for (int s = 0; s < 8; s++) {
        float p = sp[s];
        acc.x += p * v[s].x; acc.y += p * v[s].y;
        acc.z += p * v[s].z; acc.w += p * v[s].w;
    }
    float* dst = &g_U[b * H + tid * 4];
    atomicAdd(dst + 0, acc.x);
    atomicAdd(dst + 1, acc.y);
    atomicAdd(dst + 2, acc.z);
    atomicAdd(dst + 3, acc.w);
}

// fused partial GEMVs on U with 1/T folded in, PLUS last-block rels/checks
// softmax (replaces the k_rsm launch). grid (12, 12, 8), 128 threads.
__global__ void k_lin(const float* __restrict__ Wr, const float* __restrict__ Wc,
                      const float* __restrict__ Lw) {
    int tile = blockIdx.x, hc = blockIdx.y, b = blockIdx.z;
    int tid = threadIdx.x;
    int lane = tid & 31, wid = tid >> 5;   // 4 warps
    int h0 = hc * 64;
    __shared__ float sD[64];
    __shared__ float sv[NR];
    __shared__ float red4[4];
    __shared__ int   slast;
    if (tid < 64) sD[tid] = g_U[b * H + h0 + tid];
    __syncthreads();

    const float* W;
    int ncols, col0, stride, dsel;
    if (tile < 5)       { W = Wr; ncols = HOPS * NR; col0 = tile * 128;       stride = HOPS * NR; dsel = 0; }
    else if (tile == 5) { W = Wc; ncols = HOPS * 2;  col0 = 0;                stride = HOPS * 2;  dsel = 1; }
    else                { W = Lw; ncols = H;         col0 = (tile - 6) * 128; stride = H;         dsel = 2; }

    int col = col0 + tid;
    if (col < ncols) {
        const float* w = W + (size_t)h0 * stride + col;
        float a = 0.f;
        #pragma unroll 8
        for (int h = 0; h < 64; h++) a += sD[h] * w[(size_t)h * stride];
        a *= 1.f / g_T[b];
        float* dst;
        if (dsel == 0)      dst = g_Rlog + b * (HOPS * NR);
        else if (dsel == 1) dst = g_Clog + b * (HOPS * 2);
        else                dst = g_LD + b * H;
        atomicAdd(&dst[col], a);
    }

    if (tile >= 6) return;            // only Rlog/Clog writers participate

    __threadfence();
    __syncthreads();
    if (tid == 0) slast = atomicAdd(&g_cnt[b], 1);
    __syncthreads();
    if (slast != 71) return;          // 6 tiles * 12 hc = 72 contributors per b
    __threadfence();                  // acquire: see all contributors' adds

    // this block finalizes rels+checks softmax for batch b (3 hops)
    for (int hop = 0; hop < HOPS; hop++) {
        int bh = b * HOPS + hop;
        for (int i = tid; i < NR; i += 128) sv[i] = g_Rlog[bh * NR + i];
        __syncthreads();
        float m = -INFINITY;
        for (int i = tid; i < NR; i += 128) m = fmaxf(m, sv[i]);
        m = warpMax(m);
        if (lane == 0) red4[wid] = m;
        __syncthreads();
        float mx = fmaxf(fmaxf(red4[0], red4[1]), fmaxf(red4[2], red4[3]));
        float s = 0.f;
        for (int i = tid; i < NR; i += 128) {
            float e = expf(sv[i] - mx);
            sv[i] = e;
            s += e;
        }
        s = warpSum(s);
        __syncthreads();
        if (lane == 0) red4[wid] = s;
        __syncthreads();
        float Z = red4[0] + red4[1] + red4[2] + red4[3];
        for (int i = tid; i < NR; i += 128) g_R[bh * NR + i] = sv[i] / Z;
        if (tid == 0) {
            float c0 = g_Clog[bh * 2 + 0], c1 = g_Clog[bh * 2 + 1];
            float m2 = fmaxf(c0, c1);
            float e0 = expf(c0 - m2), e1 = expf(c1 - m2);
            float inv = 1.f / (e0 + e1);
            g_CS[bh * 2 + 0] = e0 * inv;
            g_CS[bh * 2 + 1] = e1 * inv;
        }
        __syncthreads();
    }
}

// ---------------- f-pass device bodies ----------------
__device__ __forceinline__ float normFac(int b, int hop) {
    float Dd = g_sums[b * HOPS + 0] + 1e-6f;
    for (int h2 = 1; h2 <= hop; h2++) Dd = g_sums[b * HOPS + h2] + 1e-6f * Dd;
    return 1.f / Dd;
}

// sum(raw) + max(raw*sc) for chunk c of (b,hop); 256 threads
__device__ void f1_body(int c, int b, int hop) {
    int tid = threadIdx.x;
    int lane = tid & 31, wid = tid >> 5;
    __shared__ float redS[8], redM[8];
    int bh = b * HOPS + hop;
    const float* wr = g_walkraw + (size_t)bh * NE + c * 2500;
    const float* sc = g_scores + (size_t)b * NE + c * 2500;
    float s = 0.f, m = -1e30f;
    for (int e = tid; e < 2500; e += 256) {
        float w = wr[e];
        s += w;
        m = fmaxf(m, w * sc[e]);
    }
    s = warpSum(s);
    m = warpMax(m);
    if (lane == 0) { redS[wid] = s; redM[wid] = m; }
    __syncthreads();
    if (tid == 0) {
        float ss = 0.f, mm = redM[0];
        #pragma unroll
        for (int i = 0; i < 8; i++) { ss += redS[i]; mm = fmaxf(mm, redM[i]); }
        atomicAdd(&g_sums[bh], ss);
        atomicMaxF(&g_mx[bh], mm);
    }
}

// exp -> g_ebuf + esum for chunk c of (b,hop); 256 threads
__device__ void f2_body(int c, int b, int hop) {
    int tid = threadIdx.x;
    int lane = tid & 31, wid = tid >> 5;
    __shared__ float red[8];
    int bh = b * HOPS + hop;
    float fac = normFac(b, hop);
    float mx = g_mx[bh] * fac;
    const float* wr = g_walkraw + (size_t)bh * NE + c * 2500;
    const float* sc = g_scores + (size_t)b * NE + c * 2500;
    float* eb = g_ebuf + (size_t)bh * NE + c * 2500;
    float s = 0.f;
    for (int e = tid; e < 2500; e += 256) {
        float v = expf(wr[e] * fac * sc[e] - mx);
        eb[e] = v;
        s += v;
    }
    s = warpSum(s);
    if (lane == 0) red[wid] = s;
    __syncthreads();
    if (tid == 0) {
        float ss = 0.f;
        #pragma unroll
        for (int i = 0; i < 8; i++) ss += red[i];
        atomicAdd(&g_esum[bh], ss);
    }
}

// combine -> out for chunk c of (b,hop); 256 threads
__device__ void f3_body(int c, int b, int hop, float* __restrict__ out) {
    int tid = threadIdx.x;
    int bh = b * HOPS + hop;
    float fac = normFac(b, hop);
    float einv = 1.f / g_esum[bh];
    float c0 = g_CS[bh * 2 + 0];
    float c1 = g_CS[bh * 2 + 1];
    const float* wr = g_walkraw + (size_t)bh * NE + c * 2500;
    const float* eb = g_ebuf + (size_t)bh * NE + c * 2500;
    float* o = out + (size_t)bh * NE + c * 2500;
    for (int e = tid; e < 2500; e += 256)
        o[e] = c0 * wr[e] * fac + c1 * eb[e] * einv;
}

// scatter body for one hop (sb in [0,3125)); 256 threads
__device__ void scatter_body(int hop, int sb, const float* __restrict__ init_ent,
                             const int* __restrict__ heads, const int* __restrict__ rels,
                             const int* __restrict__ tails) {
    int idx = sb * 256 + threadIdx.x;   // < 800000
    int b = idx / NT;
    int h = heads[idx];
    int r = rels[idx];
    int t = tails[idx];
    float prev = (hop == 0) ? init_ent[b * NE + h]
                            : g_walkraw[(size_t)(b * HOPS + hop - 1) * NE + h];
    float trip = g_R[(b * HOPS + hop) * NR + r] * prev;
    atomicAdd(&g_walkraw[(size_t)(b * HOPS + hop) * NE + t], trip);
}

// ---------------- fused launches ----------------

// hop-0 scatter + ALL scores, STRIPED 5:4 (9-block groups; 5625 blocks)
__global__ void k_sc0(const float* __restrict__ init_ent,
                      const int* __restrict__ heads, const int* __restrict__ rels,
                      const int* __restrict__ tails, const float* __restrict__ EE) {
    __shared__ float4 sLD[B * 192];
    int j = blockIdx.x % 9, g = blockIdx.x / 9;
    int tid = threadIdx.x;              // 256
    int lane = tid & 31, wid = tid >> 5;

    if (j < 5) {
        scatter_body(0, g * 5 + j, init_ent, heads, rels, tails);
    } else {
        const float4* LD4 = (const float4*)g_LD;
        for (int i = tid; i < B * 192; i += 256) sLD[i] = LD4[i];
        __syncthreads();
        int e = (g * 4 + (j - 5)) * 8 + wid;
        const float4* base = (const float4*)(EE + (size_t)e * 3072);
        float acc[B];
        #pragma unroll
        for (int b = 0; b < B; b++) acc[b] = 0.f;
        #pragma unroll
        for (int it = 0; it < 6; it++) {
            int jj = lane + it * 32;
            float4 v0 = base[jj], v1 = base[jj + 192], v2 = base[jj + 384], v3 = base[jj + 576];
            float4 sx;
            sx.x = v0.x + v1.x + v2.x + v3.x;
            sx.y = v0.y + v1.y + v2.y + v3.y;
            sx.z = v0.z + v1.z + v2.z + v3.z;
            sx.w = v0.w + v1.w + v2.w + v3.w;
            #pragma unroll
            for (int b = 0; b < B; b++) {
                float4 l = sLD[b * 192 + jj];
                acc[b] += sx.x * l.x + sx.y * l.y + sx.z * l.z + sx.w * l.w;
            }
        }
        #pragma unroll
        for (int b = 0; b < B; b++) {
            float v = warpSum(acc[b]);
            if (lane == 0) g_scores[b * NE + e] = v;
        }
    }
}

// scatter hop1 + f1(hop0) striped: groups of 50 (49 scatter + 1 f1), 64 groups
__global__ void k_s1f(const int* __restrict__ heads, const int* __restrict__ rels,
                      const int* __restrict__ tails) {
    int j = blockIdx.x % 50, g = blockIdx.x / 50;
    if (j < 49) {
        int sb = g * 49 + j;
        if (sb < 3125) scatter_body(1, sb, nullptr, heads, rels, tails);
    } else {
        f1_body(g & 7, g >> 3, 0);
    }
}

// scatter hop2 + f1(hop1) + f2(hop0) striped: groups of 51, 64 groups
__global__ void k_s2f(const int* __restrict__ heads, const int* __restrict__ rels,
                      const int* __restrict__ tails) {
    int j = blockIdx.x % 51, g = blockIdx.x / 51;
    if (j < 49) {
        int sb = g * 49 + j;
        if (sb < 3125) scatter_body(2, sb, nullptr, heads, rels, tails);
    } else if (j == 49) {
        f1_body(g & 7, g >> 3, 1);
    } else {
        f2_body(g & 7, g >> 3, 0);
    }
}

// tail A: f1(h2) | f2(h1)  — 128 blocks
__global__ void k_fa() {
    int sec = blockIdx.x >> 6, g = blockIdx.x & 63;
    if (sec == 0) f1_body(g & 7, g >> 3, 2);
    else          f2_body(g & 7, g >> 3, 1);
}

// tail B: f2(h2) | f3(h0) | f3(h1)  — 192 blocks
__global__ void k_fb(float* __restrict__ out) {
    int sec = blockIdx.x >> 6, g = blockIdx.x & 63;
    if (sec == 0)      f2_body(g & 7, g >> 3, 2);
    else if (sec == 1) f3_body(g & 7, g >> 3, 0, out);
    else               f3_body(g & 7, g >> 3, 1, out);
}

// tail C: f3(h2) — 64 blocks
__global__ void k_fc(float* __restrict__ out) {
    int g = blockIdx.x;
    f3_body(g & 7, g >> 3, 2, out);
}

// ---------------- launcher ----------------
extern "C" void kernel_launch(void* const* d_in, const int* in_sizes, int n_in,
                              void* d_out, int out_size) {
    const float* lhs      = (const float*)d_in[0];
    const float* mask     = (const float*)d_in[1];
    const float* init_ent = (const float*)d_in[2];
    const float* EE       = (const float*)d_in[3];
    // d_in[4] = W_q  (eliminated: constant term cancels in pointer softmax)
    const float* Wv       = (const float*)d_in[5];
    const float* Wp       = (const float*)d_in[6];
    const float* Wr       = (const float*)d_in[7];
    const float* Wc       = (const float*)d_in[8];
    const float* Lw       = (const float*)d_in[9];
    const int*   heads    = (const int*)d_in[10];
    const int*   rels     = (const int*)d_in[11];
    const int*   tails    = (const int*)d_in[12];
    float* out = (float*)d_out;

    k_init  <<<1875, 256>>>(Wv, Wp);                        // 1
    { dim3 g(32, B); k_D <<<g, 192>>>(lhs, mask); }         // 2
    { dim3 g(12, 12, 8); k_lin <<<g, 128>>>(Wr, Wc, Lw); }  // 3 (incl. rsm last-block)
    k_sc0   <<<5625, 256>>>(init_ent, heads, rels, tails, EE); // 4 (profiled slot)
    k_s1f   <<<3200, 256>>>(heads, rels, tails);            // 5
    k_s2f   <<<3264, 256>>>(heads, rels, tails);            // 6
    k_fa    <<<128, 256>>>();                               // 7
    k_fb    <<<192, 256>>>(out);                            // 8
    k_fc    <<<64, 256>>>(out);                             // 9
}

// round 15
// speedup vs baseline: 1.1155x; 1.1155x over previous
#include <cuda_runtime.h>
#include <math.h>

#define B    8
#define S    256
#define H    768
#define P    256
#define NE   20000
#define NT   100000
#define NR   200
#define HOPS 3

// ---------------- scratch (device globals) ----------------
__device__ float g_wvp[H];
__device__ float g_U[B * H];                 // unnormalized D (atomic acc)
__device__ float g_T[B];                     // softmax denominator per b
__device__ float g_Rlog[B * HOPS * NR];
__device__ float g_Clog[B * HOPS * 2];
__device__ float g_R[B * HOPS * NR];
__device__ float g_CS[B * HOPS * 2];
__device__ float g_LD[B * H];
__device__ float g_walkraw[B * HOPS * NE];   // RAW chained segment sums
__device__ float g_scores[B * NE];
__device__ float g_sums[B * HOPS];
__device__ float g_mx[B * HOPS];
__device__ float g_esum[B * HOPS];
__device__ float g_ebuf[B * HOPS * NE];

// ---------------- helpers ----------------
__device__ __forceinline__ float warpSum(float v) {
    #pragma unroll
    for (int o = 16; o; o >>= 1) v += __shfl_xor_sync(0xffffffffu, v, o);
    return v;
}
__device__ __forceinline__ float warpMax(float v) {
    #pragma unroll
    for (int o = 16; o; o >>= 1) v = fmaxf(v, __shfl_xor_sync(0xffffffffu, v, o));
    return v;
}
__device__ __forceinline__ void atomicMaxF(float* addr, float val) {
    int old = __float_as_int(*addr);
    while (__int_as_float(old) < val) {
        int assumed = old;
        old = atomicCAS((int*)addr, assumed, __float_as_int(val));
        if (old == assumed) break;
    }
}

// ---------------- kernels ----------------

// zero atomic-accumulated scratch; first 768 warps compute wvp = W_v @ W_p
__global__ void k_init(const float* __restrict__ Wv, const float* __restrict__ Wp) {
    int idx = blockIdx.x * blockDim.x + threadIdx.x;          // 1875*256
    if (idx < B * HOPS * NE) g_walkraw[idx] = 0.f;
    if (idx < B * H) { g_U[idx] = 0.f; g_LD[idx] = 0.f; }
    if (idx < B * HOPS * NR) g_Rlog[idx] = 0.f;
    if (idx < B * HOPS * 2) g_Clog[idx] = 0.f;
    if (idx < B * HOPS) { g_sums[idx] = 0.f; g_esum[idx] = 0.f; g_mx[idx] = -1e30f; }
    if (idx < B) g_T[idx] = 0.f;
    int warp = idx >> 5;
    int lane = threadIdx.x & 31;
    if (warp < H) {
        float acc = 0.f;
        #pragma unroll
        for (int p = lane; p < P; p += 32) acc += Wv[warp * P + p] * Wp[p];
        acc = warpSum(acc);
        if (lane == 0) g_wvp[warp] = acc;
    }
}

// single-pass: block holds 8 lhs rows in REGISTERS, computes logits + exp
// (no max-subtraction: softmax shift-invariant, logits ~ N(0,1)),
// accumulates U[b,h] += e*mask*x and T[b] += e. grid (32, B), 192 threads.
__global__ void k_D(const float* __restrict__ lhs, const float* __restrict__ mask) {
    int sc = blockIdx.x, b = blockIdx.y;
    int tid = threadIdx.x;                 // 192 = 6 warps
    int lane = tid & 31, wid = tid >> 5;
    __shared__ float red[8][6];
    __shared__ float sp[8];

    float4 w = ((const float4*)g_wvp)[tid];
    int s0 = sc * 8;
    const float4* base = (const float4*)(lhs + ((size_t)(b * S + s0)) * H) + tid;
    float4 v[8];
    float part[8];
    #pragma unroll
    for (int s = 0; s < 8; s++) {
        v[s] = base[(size_t)s * (H / 4)];
        part[s] = v[s].x * w.x + v[s].y * w.y + v[s].z * w.z + v[s].w * w.w;
    }
    #pragma unroll
    for (int s = 0; s < 8; s++) {
        float r = warpSum(part[s]);
        if (lane == 0) red[s][wid] = r;
    }
    __syncthreads();
    if (tid < 8) {
        float l = red[tid][0] + red[tid][1] + red[tid][2]
                + red[tid][3] + red[tid][4] + red[tid][5];
        float e = expf(l);
        sp[tid] = e * mask[b * S + s0 + tid];
        red[tid][0] = e;
    }
    __syncthreads();
    if (tid == 0) {
        float t = 0.f;
        #pragma unroll
        for (int s = 0; s < 8; s++) t += red[s][0];
        atomicAdd(&g_T[b], t);
    }
    float4 acc = make_float4(0.f, 0.f, 0.f, 0.f);
    #pragma unroll
    for (int s = 0; s < 8; s++) {
        float p = sp[s];
        acc.x += p * v[s].x; acc.y += p * v[s].y;
        acc.z += p * v[s].z; acc.w += p * v[s].w;
    }
    float* dst = &g_U[b * H + tid * 4];
    atomicAdd(dst + 0, acc.x);
    atomicAdd(dst + 1, acc.y);
    atomicAdd(dst + 2, acc.z);
    atomicAdd(dst + 3, acc.w);
}

// fused partial GEMVs on U with 1/T folded in: (U/T) @ {Wr,Wc,Lw}.
// grid (12 col-tiles, 12 h-chunks of 64, 8 b), 128 threads
__global__ void k_lin(const float* __restrict__ Wr, const float* __restrict__ Wc,
                      const float* __restrict__ Lw) {
    int tile = blockIdx.x, hc = blockIdx.y, b = blockIdx.z;
    int tid = threadIdx.x;
    int h0 = hc * 64;
    __shared__ float sD[64];
    if (tid < 64) sD[tid] = g_U[b * H + h0 + tid];
    __syncthreads();

    const float* W;
    int ncols, col0, stride, dsel;
    if (tile < 5)       { W = Wr; ncols = HOPS * NR; col0 = tile * 128;       stride = HOPS * NR; dsel = 0; }
    else if (tile == 5) { W = Wc; ncols = HOPS * 2;  col0 = 0;                stride = HOPS * 2;  dsel = 1; }
    else                { W = Lw; ncols = H;         col0 = (tile - 6) * 128; stride = H;         dsel = 2; }

    int col = col0 + tid;
    if (col >= ncols) return;
    const float* w = W + (size_t)h0 * stride + col;
    float a = 0.f;
    #pragma unroll 8
    for (int h = 0; h < 64; h++) a += sD[h] * w[(size_t)h * stride];
    a *= 1.f / g_T[b];                       // fold softmax denominator
    float* dst;
    if (dsel == 0)      dst = g_Rlog + b * (HOPS * NR);
    else if (dsel == 1) dst = g_Clog + b * (HOPS * 2);
    else                dst = g_LD + b * H;
    atomicAdd(&dst[col], a);
}

// softmax rels (200) + checks (2) per (b,hop)
__global__ void k_rsm() {
    int bh = blockIdx.x;
    int tid = threadIdx.x;   // 256
    int lane = tid & 31, wid = tid >> 5;
    __shared__ float red[8];
    float v = (tid < NR) ? g_Rlog[bh * NR + tid] : -INFINITY;
    float m = warpMax(v);
    if (lane == 0) red[wid] = m;
    __syncthreads();
    if (tid == 0) {
        float mm = red[0];
        #pragma unroll
        for (int i = 1; i < 8; i++) mm = fmaxf(mm, red[i]);
        red[0] = mm;
    }
    __syncthreads();
    float mx = red[0];
    __syncthreads();
    float e = (tid < NR) ? expf(v - mx) : 0.f;
    float s = warpSum(e);
    if (lane == 0) red[wid] = s;
    __syncthreads();
    if (tid == 0) {
        float ss = 0.f;
        #pragma unroll
        for (int i = 0; i < 8; i++) ss += red[i];
        red[0] = ss;
    }
    __syncthreads();
    if (tid < NR) g_R[bh * NR + tid] = e / red[0];
    if (tid == 0) {
        float c0 = g_Clog[bh * 2 + 0], c1 = g_Clog[bh * 2 + 1];
        float m2 = fmaxf(c0, c1);
        float e0 = expf(c0 - m2), e1 = expf(c1 - m2);
        float inv = 1.f / (e0 + e1);
        g_CS[bh * 2 + 0] = e0 * inv;
        g_CS[bh * 2 + 1] = e1 * inv;
    }
}

// fused hop-0 scatter + ALL scores, STRIPED 4:5 (scores gets the larger SM share;
// it is the DRAM-bound side at 70.7% DRAM in R14's profile).
// 9-block groups, 782 groups = 7038 blocks; scatter sb = g*4+j (<3125),
// scores qb = g*5+(j-4) (<2500; excess blocks exit immediately).
__global__ void k_sc0(const float* __restrict__ init_ent,
                      const int* __restrict__ heads, const int* __restrict__ rels,
                      const int* __restrict__ tails, const float* __restrict__ EE) {
    __shared__ float4 sLD[B * 192];
    int j = blockIdx.x % 9, g = blockIdx.x / 9;
    int tid = threadIdx.x;              // 256
    int lane = tid & 31, wid = tid >> 5;

    if (j < 4) {
        int sb = g * 4 + j;
        if (sb >= 3125) return;
        int idx = sb * 256 + tid;       // < 800000
        int b = idx / NT;
        int h = heads[idx];
        int r = rels[idx];
        int t = tails[idx];
        float trip = g_R[(b * HOPS + 0) * NR + r] * init_ent[b * NE + h];
        atomicAdd(&g_walkraw[(size_t)(b * HOPS + 0) * NE + t], trip);
    } else {
        int qb = g * 5 + (j - 4);
        if (qb >= 2500) return;
        const float4* LD4 = (const float4*)g_LD;
        for (int i = tid; i < B * 192; i += 256) sLD[i] = LD4[i];
        __syncthreads();
        int e = qb * 8 + wid;
        const float4* base = (const float4*)(EE + (size_t)e * 3072);
        float acc[B];
        #pragma unroll
        for (int b = 0; b < B; b++) acc[b] = 0.f;
        #pragma unroll
        for (int it = 0; it < 6; it++) {
            int jj = lane + it * 32;
            float4 v0 = base[jj], v1 = base[jj + 192], v2 = base[jj + 384], v3 = base[jj + 576];
            float4 sx;
            sx.x = v0.x + v1.x + v2.x + v3.x;
            sx.y = v0.y + v1.y + v2.y + v3.y;
            sx.z = v0.z + v1.z + v2.z + v3.z;
            sx.w = v0.w + v1.w + v2.w + v3.w;
            #pragma unroll
            for (int b = 0; b < B; b++) {
                float4 l = sLD[b * 192 + jj];
                acc[b] += sx.x * l.x + sx.y * l.y + sx.z * l.z + sx.w * l.w;
            }
        }
        #pragma unroll
        for (int b = 0; b < B; b++) {
            float v = warpSum(acc[b]);
            if (lane == 0) g_scores[b * NE + e] = v;
        }
    }
}

// hops 1,2 RAW chaining: trip = R[b,hop,rel] * raw_prev[head]; scatter-add by tail.
__global__ void k_scatter(int hop, const int* __restrict__ heads,
                          const int* __restrict__ rels,
                          const int* __restrict__ tails) {
    int idx = blockIdx.x * blockDim.x + threadIdx.x;   // exactly 800000
    int b = idx / NT;
    int h = heads[idx];
    int r = rels[idx];
    int t = tails[idx];
    float prev = g_walkraw[(size_t)(b * HOPS + hop - 1) * NE + h];
    float trip = g_R[(b * HOPS + hop) * NR + r] * prev;
    atomicAdd(&g_walkraw[(size_t)(b * HOPS + hop) * NE + t], trip);
}

// pass 1: per-(b,hop) sum(raw) and max(raw*sc) in ONE sweep — grid (8, 24)
__global__ void k_f1() {
    int c = blockIdx.x, bh = blockIdx.y;
    int b = bh / HOPS;
    int tid = threadIdx.x;  // 256
    int lane = tid & 31, wid = tid >> 5;
    __shared__ float redS[8], redM[8];
    const float* wr = g_walkraw + (size_t)bh * NE + c * 2500;
    const float* sc = g_scores + (size_t)b * NE + c * 2500;
    float s = 0.f, m = -1e30f;
    for (int e = tid; e < 2500; e += 256) {
        float w = wr[e];
        s += w;
        m = fmaxf(m, w * sc[e]);
    }
    s = warpSum(s);
    m = warpMax(m);
    if (lane == 0) { redS[wid] = s; redM[wid] = m; }
    __syncthreads();
    if (tid == 0) {
        float ss = 0.f, mm = redM[0];
        #pragma unroll
        for (int i = 0; i < 8; i++) { ss += redS[i]; mm = fmaxf(mm, redM[i]); }
        atomicAdd(&g_sums[bh], ss);
        atomicMaxF(&g_mx[bh], mm);
    }
}

// epsilon chain: D0 = s0+1e-6; Dh = sh + 1e-6*D(h-1); normalized = raw/Dh
__device__ __forceinline__ float normFac(int b, int hop) {
    float Dd = g_sums[b * HOPS + 0] + 1e-6f;
    for (int h2 = 1; h2 <= hop; h2++) Dd = g_sums[b * HOPS + h2] + 1e-6f * Dd;
    return 1.f / Dd;
}

// pass 2: exp -> g_ebuf + esum — grid (8, 24)
__global__ void k_f2() {
    int c = blockIdx.x, bh = blockIdx.y;
    int b = bh / HOPS, hop = bh % HOPS;
    int tid = threadIdx.x;  // 256
    int lane = tid & 31, wid = tid >> 5;
    __shared__ float red[8];
    float fac = normFac(b, hop);
    float mx = g_mx[bh] * fac;
    const float* wr = g_walkraw + (size_t)bh * NE + c * 2500;
    const float* sc = g_scores + (size_t)b * NE + c * 2500;
    float* eb = g_ebuf + (size_t)bh * NE + c * 2500;
    float s = 0.f;
    for (int e = tid; e < 2500; e += 256) {
        float v = expf(wr[e] * fac * sc[e] - mx);
        eb[e] = v;
        s += v;
    }
    s = warpSum(s);
    if (lane == 0) red[wid] = s;
    __syncthreads();
    if (tid == 0) {
        float ss = 0.f;
        #pragma unroll
        for (int i = 0; i < 8; i++) ss += red[i];
        atomicAdd(&g_esum[bh], ss);
    }
}

// pass 3: combine -> out — grid (8, 24)
__global__ void k_f3(float* __restrict__ out) {
    int c = blockIdx.x, bh = blockIdx.y;
    int b = bh / HOPS, hop = bh % HOPS;
    int tid = threadIdx.x;  // 256
    float fac = normFac(b, hop);
    float einv = 1.f / g_esum[bh];
    float c0 = g_CS[bh * 2 + 0];
    float c1 = g_CS[bh * 2 + 1];
    const float* wr = g_walkraw + (size_t)bh * NE + c * 2500;
    const float* eb = g_ebuf + (size_t)bh * NE + c * 2500;
    float* o = out + (size_t)bh * NE + c * 2500;
    for (int e = tid; e < 2500; e += 256)
        o[e] = c0 * wr[e] * fac + c1 * eb[e] * einv;
}

// ---------------- launcher ----------------
extern "C" void kernel_launch(void* const* d_in, const int* in_sizes, int n_in,
                              void* d_out, int out_size) {
    const float* lhs      = (const float*)d_in[0];
    const float* mask     = (const float*)d_in[1];
    const float* init_ent = (const float*)d_in[2];
    const float* EE       = (const float*)d_in[3];
    // d_in[4] = W_q  (eliminated: constant term cancels in pointer softmax)
    const float* Wv       = (const float*)d_in[5];
    const float* Wp       = (const float*)d_in[6];
    const float* Wr       = (const float*)d_in[7];
    const float* Wc       = (const float*)d_in[8];
    const float* Lw       = (const float*)d_in[9];
    const int*   heads    = (const int*)d_in[10];
    const int*   rels     = (const int*)d_in[11];
    const int*   tails    = (const int*)d_in[12];
    float* out = (float*)d_out;

    k_init  <<<1875, 256>>>(Wv, Wp);                        // 1
    { dim3 g(32, B); k_D <<<g, 192>>>(lhs, mask); }         // 2
    { dim3 g(12, 12, 8); k_lin <<<g, 128>>>(Wr, Wc, Lw); }  // 3
    k_rsm   <<<B * HOPS, 256>>>();                          // 4
    k_sc0   <<<7038, 256>>>(init_ent, heads, rels, tails, EE); // 5
    k_scatter<<<3125, 256>>>(1, heads, rels, tails);        // 6
    k_scatter<<<3125, 256>>>(2, heads, rels, tails);        // 7
    { dim3 g(8, B * HOPS); k_f1<<<g, 256>>>(); }            // 8
    { dim3 g(8, B * HOPS); k_f2<<<g, 256>>>(); }            // 9
    { dim3 g(8, B * HOPS); k_f3<<<g, 256>>>(out); }         // 10
}

// round 16
// speedup vs baseline: 1.1389x; 1.0210x over previous
#include <cuda_runtime.h>
#include <math.h>

#define B    8
#define S    256
#define H    768
#define P    256
#define NE   20000
#define NT   100000
#define NR   200
#define HOPS 3

// ---------------- scratch (device globals) ----------------
__device__ float g_wvp[H];
__device__ float g_U[B * H];                 // unnormalized D (atomic acc)
__device__ float g_T[B];                     // pointer-softmax denominator per b
__device__ float g_Rlog[B * HOPS * NR];      // rels LOGITS (softmax cancels in walk)
__device__ float g_Clog[B * HOPS * 2];       // checks logits
__device__ float g_LD[B * H];
__device__ float g_walkraw[B * HOPS * NE];   // RAW chained segment sums
__device__ float g_scores[B * NE];
__device__ float g_sums[B * HOPS];
__device__ float g_mx[B * HOPS];
__device__ float g_esum[B * HOPS];
__device__ float g_ebuf[B * HOPS * NE];

// ---------------- helpers ----------------
__device__ __forceinline__ float warpSum(float v) {
    #pragma unroll
    for (int o = 16; o; o >>= 1) v += __shfl_xor_sync(0xffffffffu, v, o);
    return v;
}
__device__ __forceinline__ float warpMax(float v) {
    #pragma unroll
    for (int o = 16; o; o >>= 1) v = fmaxf(v, __shfl_xor_sync(0xffffffffu, v, o));
    return v;
}
__device__ __forceinline__ void atomicMaxF(float* addr, float val) {
    int old = __float_as_int(*addr);
    while (__int_as_float(old) < val) {
        int assumed = old;
        old = atomicCAS((int*)addr, assumed, __float_as_int(val));
        if (old == assumed) break;
    }
}

// ---------------- kernels ----------------

// zero atomic-accumulated scratch; first 768 warps compute wvp = W_v @ W_p
__global__ void k_init(const float* __restrict__ Wv, const float* __restrict__ Wp) {
    int idx = blockIdx.x * blockDim.x + threadIdx.x;          // 1875*256
    if (idx < B * HOPS * NE) g_walkraw[idx] = 0.f;
    if (idx < B * H) { g_U[idx] = 0.f; g_LD[idx] = 0.f; }
    if (idx < B * HOPS * NR) g_Rlog[idx] = 0.f;
    if (idx < B * HOPS * 2) g_Clog[idx] = 0.f;
    if (idx < B * HOPS) { g_sums[idx] = 0.f; g_esum[idx] = 0.f; g_mx[idx] = -1e30f; }
    if (idx < B) g_T[idx] = 0.f;
    int warp = idx >> 5;
    int lane = threadIdx.x & 31;
    if (warp < H) {
        float acc = 0.f;
        #pragma unroll
        for (int p = lane; p < P; p += 32) acc += Wv[warp * P + p] * Wp[p];
        acc = warpSum(acc);
        if (lane == 0) g_wvp[warp] = acc;
    }
}

// single-pass: block holds 8 lhs rows in REGISTERS, computes logits + exp
// (no max-subtraction: softmax shift-invariant, logits ~ N(0,1)),
// accumulates U[b,h] += e*mask*x and T[b] += e. grid (32, B), 192 threads.
__global__ void k_D(const float* __restrict__ lhs, const float* __restrict__ mask) {
    int sc = blockIdx.x, b = blockIdx.y;
    int tid = threadIdx.x;                 // 192 = 6 warps
    int lane = tid & 31, wid = tid >> 5;
    __shared__ float red[8][6];
    __shared__ float sp[8];

    float4 w = ((const float4*)g_wvp)[tid];
    int s0 = sc * 8;
    const float4* base = (const float4*)(lhs + ((size_t)(b * S + s0)) * H) + tid;
    float4 v[8];
    float part[8];
    #pragma unroll
    for (int s = 0; s < 8; s++) {
        v[s] = base[(size_t)s * (H / 4)];
        part[s] = v[s].x * w.x + v[s].y * w.y + v[s].z * w.z + v[s].w * w.w;
    }
    #pragma unroll
    for (int s = 0; s < 8; s++) {
        float r = warpSum(part[s]);
        if (lane == 0) red[s][wid] = r;
    }
    __syncthreads();
    if (tid < 8) {
        float l = red[tid][0] + red[tid][1] + red[tid][2]
                + red[tid][3] + red[tid][4] + red[tid][5];
        float e = expf(l);
        sp[tid] = e * mask[b * S + s0 + tid];
        red[tid][0] = e;
    }
    __syncthreads();
    if (tid == 0) {
        float t = 0.f;
        #pragma unroll
        for (int s = 0; s < 8; s++) t += red[s][0];
        atomicAdd(&g_T[b], t);
    }
    float4 acc = make_float4(0.f, 0.f, 0.f, 0.f);
    #pragma unroll
    for (int s = 0; s < 8; s++) {
        float p = sp[s];
        acc.x += p * v[s].x; acc.y += p * v[s].y;
        acc.z += p * v[s].z; acc.w += p * v[s].w;
    }
    float* dst = &g_U[b * H + tid * 4];
    atomicAdd(dst + 0, acc.x);
    atomicAdd(dst + 1, acc.y);
    atomicAdd(dst + 2, acc.z);
    atomicAdd(dst + 3, acc.w);
}

// fused partial GEMVs on U with 1/T folded in: (U/T) @ {Wr,Wc,Lw}.
// grid (12 col-tiles, 12 h-chunks of 64, 8 b), 128 threads
__global__ void k_lin(const float* __restrict__ Wr, const float* __restrict__ Wc,
                      const float* __restrict__ Lw) {
    int tile = blockIdx.x, hc = blockIdx.y, b = blockIdx.z;
    int tid = threadIdx.x;
    int h0 = hc * 64;
    __shared__ float sD[64];
    if (tid < 64) sD[tid] = g_U[b * H + h0 + tid];
    __syncthreads();

    const float* W;
    int ncols, col0, stride, dsel;
    if (tile < 5)       { W = Wr; ncols = HOPS * NR; col0 = tile * 128;       stride = HOPS * NR; dsel = 0; }
    else if (tile == 5) { W = Wc; ncols = HOPS * 2;  col0 = 0;                stride = HOPS * 2;  dsel = 1; }
    else                { W = Lw; ncols = H;         col0 = (tile - 6) * 128; stride = H;         dsel = 2; }

    int col = col0 + tid;
    if (col >= ncols) return;
    const float* w = W + (size_t)h0 * stride + col;
    float a = 0.f;
    #pragma unroll 8
    for (int h = 0; h < 64; h++) a += sD[h] * w[(size_t)h * stride];
    a *= 1.f / g_T[b];                       // fold softmax denominator
    float* dst;
    if (dsel == 0)      dst = g_Rlog + b * (HOPS * NR);
    else if (dsel == 1) dst = g_Clog + b * (HOPS * 2);
    else                dst = g_LD + b * H;
    atomicAdd(&dst[col], a);
}

// fused hop-0 scatter + ALL scores, STRIPED 4:5 (scores = DRAM-bound majority side).
// 9-block groups, 782 groups = 7038 blocks.
// Scatter uses UNNORMALIZED rels: trip = exp(Rlog) * init — softmax Z cancels
// through the walk normalization (eps-shift error ~4e-9 relative).
__global__ void k_sc0(const float* __restrict__ init_ent,
                      const int* __restrict__ heads, const int* __restrict__ rels,
                      const int* __restrict__ tails, const float* __restrict__ EE) {
    __shared__ float4 sLD[B * 192];
    int j = blockIdx.x % 9, g = blockIdx.x / 9;
    int tid = threadIdx.x;              // 256
    int lane = tid & 31, wid = tid >> 5;

    if (j < 4) {
        int sb = g * 4 + j;
        if (sb >= 3125) return;
        int idx = sb * 256 + tid;       // < 800000
        int b = idx / NT;
        int h = heads[idx];
        int r = rels[idx];
        int t = tails[idx];
        float trip = expf(g_Rlog[(b * HOPS + 0) * NR + r]) * init_ent[b * NE + h];
        atomicAdd(&g_walkraw[(size_t)(b * HOPS + 0) * NE + t], trip);
    } else {
        int qb = g * 5 + (j - 4);
        if (qb >= 2500) return;
        const float4* LD4 = (const float4*)g_LD;
        for (int i = tid; i < B * 192; i += 256) sLD[i] = LD4[i];
        __syncthreads();
        int e = qb * 8 + wid;
        const float4* base = (const float4*)(EE + (size_t)e * 3072);
        float acc[B];
        #pragma unroll
        for (int b = 0; b < B; b++) acc[b] = 0.f;
        #pragma unroll
        for (int it = 0; it < 6; it++) {
            int jj = lane + it * 32;
            float4 v0 = base[jj], v1 = base[jj + 192], v2 = base[jj + 384], v3 = base[jj + 576];
            float4 sx;
            sx.x = v0.x + v1.x + v2.x + v3.x;
            sx.y = v0.y + v1.y + v2.y + v3.y;
            sx.z = v0.z + v1.z + v2.z + v3.z;
            sx.w = v0.w + v1.w + v2.w + v3.w;
            #pragma unroll
            for (int b = 0; b < B; b++) {
                float4 l = sLD[b * 192 + jj];
                acc[b] += sx.x * l.x + sx.y * l.y + sx.z * l.z + sx.w * l.w;
            }
        }
        #pragma unroll
        for (int b = 0; b < B; b++) {
            float v = warpSum(acc[b]);
            if (lane == 0) g_scores[b * NE + e] = v;
        }
    }
}

// hops 1,2 RAW chaining with unnormalized rels:
// trip = exp(Rlog[b,hop,r]) * raw_prev[head]; scatter-add by tail.
__global__ void k_scatter(int hop, const int* __restrict__ heads,
                          const int* __restrict__ rels,
                          const int* __restrict__ tails) {
    int idx = blockIdx.x * blockDim.x + threadIdx.x;   // exactly 800000
    int b = idx / NT;
    int h = heads[idx];
    int r = rels[idx];
    int t = tails[idx];
    float prev = g_walkraw[(size_t)(b * HOPS + hop - 1) * NE + h];
    float trip = expf(g_Rlog[(b * HOPS + hop) * NR + r]) * prev;
    atomicAdd(&g_walkraw[(size_t)(b * HOPS + hop) * NE + t], trip);
}

// pass 1: per-(b,hop) sum(raw) and max(raw*sc) in ONE sweep — grid (8, 24)
__global__ void k_f1() {
    int c = blockIdx.x, bh = blockIdx.y;
    int b = bh / HOPS;
    int tid = threadIdx.x;  // 256
    int lane = tid & 31, wid = tid >> 5;
    __shared__ float redS[8], redM[8];
    const float* wr = g_walkraw + (size_t)bh * NE + c * 2500;
    const float* sc = g_scores + (size_t)b * NE + c * 2500;
    float s = 0.f, m = -1e30f;
    for (int e = tid; e < 2500; e += 256) {
        float w = wr[e];
        s += w;
        m = fmaxf(m, w * sc[e]);
    }
    s = warpSum(s);
    m = warpMax(m);
    if (lane == 0) { redS[wid] = s; redM[wid] = m; }
    __syncthreads();
    if (tid == 0) {
        float ss = 0.f, mm = redM[0];
        #pragma unroll
        for (int i = 0; i < 8; i++) { ss += redS[i]; mm = fmaxf(mm, redM[i]); }
        atomicAdd(&g_sums[bh], ss);
        atomicMaxF(&g_mx[bh], mm);
    }
}

// epsilon chain: D0 = s0+1e-6; Dh = sh + 1e-6*D(h-1); normalized = raw/Dh
__device__ __forceinline__ float normFac(int b, int hop) {
    float Dd = g_sums[b * HOPS + 0] + 1e-6f;
    for (int h2 = 1; h2 <= hop; h2++) Dd = g_sums[b * HOPS + h2] + 1e-6f * Dd;
    return 1.f / Dd;
}

// pass 2: exp -> g_ebuf + esum — grid (8, 24)
__global__ void k_f2() {
    int c = blockIdx.x, bh = blockIdx.y;
    int b = bh / HOPS, hop = bh % HOPS;
    int tid = threadIdx.x;  // 256
    int lane = tid & 31, wid = tid >> 5;
    __shared__ float red[8];
    float fac = normFac(b, hop);
    float mx = g_mx[bh] * fac;
    const float* wr = g_walkraw + (size_t)bh * NE + c * 2500;
    const float* sc = g_scores + (size_t)b * NE + c * 2500;
    float* eb = g_ebuf + (size_t)bh * NE + c * 2500;
    float s = 0.f;
    for (int e = tid; e < 2500; e += 256) {
        float v = expf(wr[e] * fac * sc[e] - mx);
        eb[e] = v;
        s += v;
    }
    s = warpSum(s);
    if (lane == 0) red[wid] = s;
    __syncthreads();
    if (tid == 0) {
        float ss = 0.f;
        #pragma unroll
        for (int i = 0; i < 8; i++) ss += red[i];
        atomicAdd(&g_esum[bh], ss);
    }
}

// pass 3: combine -> out — grid (8, 24); checks softmax (2-wide) inline
__global__ void k_f3(float* __restrict__ out) {
    int c = blockIdx.x, bh = blockIdx.y;
    int b = bh / HOPS, hop = bh % HOPS;
    int tid = threadIdx.x;  // 256
    float fac = normFac(b, hop);
    float einv = 1.f / g_esum[bh];
    float l0 = g_Clog[bh * 2 + 0], l1 = g_Clog[bh * 2 + 1];
    float m2 = fmaxf(l0, l1);
    float e0 = expf(l0 - m2), e1 = expf(l1 - m2);
    float cinv = 1.f / (e0 + e1);
    float c0 = e0 * cinv;
    float c1 = e1 * cinv;
    const float* wr = g_walkraw + (size_t)bh * NE + c * 2500;
    const float* eb = g_ebuf + (size_t)bh * NE + c * 2500;
    float* o = out + (size_t)bh * NE + c * 2500;
    for (int e = tid; e < 2500; e += 256)
        o[e] = c0 * wr[e] * fac + c1 * eb[e] * einv;
}

// ---------------- launcher ----------------
extern "C" void kernel_launch(void* const* d_in, const int* in_sizes, int n_in,
                              void* d_out, int out_size) {
    const float* lhs      = (const float*)d_in[0];
    const float* mask     = (const float*)d_in[1];
    const float* init_ent = (const float*)d_in[2];
    const float* EE       = (const float*)d_in[3];
    // d_in[4] = W_q  (eliminated: constant term cancels in pointer softmax)
    const float* Wv       = (const float*)d_in[5];
    const float* Wp       = (const float*)d_in[6];
    const float* Wr       = (const float*)d_in[7];
    const float* Wc       = (const float*)d_in[8];
    const float* Lw       = (const float*)d_in[9];
    const int*   heads    = (const int*)d_in[10];
    const int*   rels     = (const int*)d_in[11];
    const int*   tails    = (const int*)d_in[12];
    float* out = (float*)d_out;

    k_init  <<<1875, 256>>>(Wv, Wp);                        // 1
    { dim3 g(32, B); k_D <<<g, 192>>>(lhs, mask); }         // 2
    { dim3 g(12, 12, 8); k_lin <<<g, 128>>>(Wr, Wc, Lw); }  // 3
    k_sc0   <<<7038, 256>>>(init_ent, heads, rels, tails, EE); // 4 (profiled slot)
    k_scatter<<<3125, 256>>>(1, heads, rels, tails);        // 5
    k_scatter<<<3125, 256>>>(2, heads, rels, tails);        // 6
    { dim3 g(8, B * HOPS); k_f1<<<g, 256>>>(); }            // 7
    { dim3 g(8, B * HOPS); k_f2<<<g, 256>>>(); }            // 8
    { dim3 g(8, B * HOPS); k_f3<<<g, 256>>>(out); }         // 9
}

// round 17
// speedup vs baseline: 1.1415x; 1.0023x over previous
#include <cuda_runtime.h>
#include <math.h>

#define B    8
#define S    256
#define H    768
#define P    256
#define NE   20000
#define NT   100000
#define NR   200
#define HOPS 3

// ---------------- scratch (device globals) ----------------
__device__ float g_wvp[H];
__device__ float g_U[B * H];                 // unnormalized D (atomic acc)
__device__ float g_T[B];                     // pointer-softmax denominator per b
__device__ float g_Rlog[B * HOPS * NR];      // rels LOGITS (softmax cancels in walk)
__device__ float g_Clog[B * HOPS * 2];       // checks logits
__device__ float g_LD[B * H];
__device__ float g_walkraw[B * HOPS * NE];   // RAW chained segment sums
__device__ float g_scores[B * NE];
__device__ float g_sums[B * HOPS];
__device__ float g_mx[B * HOPS];
__device__ float g_esum[B * HOPS];
__device__ float g_ebuf[B * HOPS * NE];

// ---------------- helpers ----------------
__device__ __forceinline__ float warpSum(float v) {
    #pragma unroll
    for (int o = 16; o; o >>= 1) v += __shfl_xor_sync(0xffffffffu, v, o);
    return v;
}
__device__ __forceinline__ float warpMax(float v) {
    #pragma unroll
    for (int o = 16; o; o >>= 1) v = fmaxf(v, __shfl_xor_sync(0xffffffffu, v, o));
    return v;
}
__device__ __forceinline__ void atomicMaxF(float* addr, float val) {
    int old = __float_as_int(*addr);
    while (__int_as_float(old) < val) {
        int assumed = old;
        old = atomicCAS((int*)addr, assumed, __float_as_int(val));
        if (old == assumed) break;
    }
}

// ---------------- kernels ----------------

// zero atomic-accumulated scratch; first 768 warps compute wvp = W_v @ W_p
__global__ void k_init(const float* __restrict__ Wv, const float* __restrict__ Wp) {
    int idx = blockIdx.x * blockDim.x + threadIdx.x;          // 1875*256
    if (idx < B * HOPS * NE) g_walkraw[idx] = 0.f;
    if (idx < B * H) { g_U[idx] = 0.f; g_LD[idx] = 0.f; }
    if (idx < B * HOPS * NR) g_Rlog[idx] = 0.f;
    if (idx < B * HOPS * 2) g_Clog[idx] = 0.f;
    if (idx < B * HOPS) { g_sums[idx] = 0.f; g_esum[idx] = 0.f; g_mx[idx] = -1e30f; }
    if (idx < B) g_T[idx] = 0.f;
    int warp = idx >> 5;
    int lane = threadIdx.x & 31;
    if (warp < H) {
        float acc = 0.f;
        #pragma unroll
        for (int p = lane; p < P; p += 32) acc += Wv[warp * P + p] * Wp[p];
        acc = warpSum(acc);
        if (lane == 0) g_wvp[warp] = acc;
    }
}

// single-pass: block holds 8 lhs rows in REGISTERS, computes logits + exp
// (no max-subtraction: softmax shift-invariant), accumulates U and T.
// grid (32, B), 192 threads.
__global__ void k_D(const float* __restrict__ lhs, const float* __restrict__ mask) {
    int sc = blockIdx.x, b = blockIdx.y;
    int tid = threadIdx.x;                 // 192 = 6 warps
    int lane = tid & 31, wid = tid >> 5;
    __shared__ float red[8][6];
    __shared__ float sp[8];

    float4 w = ((const float4*)g_wvp)[tid];
    int s0 = sc * 8;
    const float4* base = (const float4*)(lhs + ((size_t)(b * S + s0)) * H) + tid;
    float4 v[8];
    float part[8];
    #pragma unroll
    for (int s = 0; s < 8; s++) {
        v[s] = base[(size_t)s * (H / 4)];
        part[s] = v[s].x * w.x + v[s].y * w.y + v[s].z * w.z + v[s].w * w.w;
    }
    #pragma unroll
    for (int s = 0; s < 8; s++) {
        float r = warpSum(part[s]);
        if (lane == 0) red[s][wid] = r;
    }
    __syncthreads();
    if (tid < 8) {
        float l = red[tid][0] + red[tid][1] + red[tid][2]
                + red[tid][3] + red[tid][4] + red[tid][5];
        float e = expf(l);
        sp[tid] = e * mask[b * S + s0 + tid];
        red[tid][0] = e;
    }
    __syncthreads();
    if (tid == 0) {
        float t = 0.f;
        #pragma unroll
        for (int s = 0; s < 8; s++) t += red[s][0];
        atomicAdd(&g_T[b], t);
    }
    float4 acc = make_float4(0.f, 0.f, 0.f, 0.f);
    #pragma unroll
    for (int s = 0; s < 8; s++) {
        float p = sp[s];
        acc.x += p * v[s].x; acc.y += p * v[s].y;
        acc.z += p * v[s].z; acc.w += p * v[s].w;
    }
    float* dst = &g_U[b * H + tid * 4];
    atomicAdd(dst + 0, acc.x);
    atomicAdd(dst + 1, acc.y);
    atomicAdd(dst + 2, acc.z);
    atomicAdd(dst + 3, acc.w);
}

// fused partial GEMVs on U with 1/T folded in: (U/T) @ {Wr,Wc,Lw}.
// grid (12 col-tiles, 24 h-chunks of 32, 8 b), 128 threads
__global__ void k_lin(const float* __restrict__ Wr, const float* __restrict__ Wc,
                      const float* __restrict__ Lw) {
    int tile = blockIdx.x, hc = blockIdx.y, b = blockIdx.z;
    int tid = threadIdx.x;
    int h0 = hc * 32;
    __shared__ float sD[32];
    if (tid < 32) sD[tid] = g_U[b * H + h0 + tid];
    __syncthreads();

    const float* W;
    int ncols, col0, stride, dsel;
    if (tile < 5)       { W = Wr; ncols = HOPS * NR; col0 = tile * 128;       stride = HOPS * NR; dsel = 0; }
    else if (tile == 5) { W = Wc; ncols = HOPS * 2;  col0 = 0;                stride = HOPS * 2;  dsel = 1; }
    else                { W = Lw; ncols = H;         col0 = (tile - 6) * 128; stride = H;         dsel = 2; }

    int col = col0 + tid;
    if (col >= ncols) return;
    const float* w = W + (size_t)h0 * stride + col;
    float a = 0.f;
    #pragma unroll 8
    for (int h = 0; h < 32; h++) a += sD[h] * w[(size_t)h * stride];
    a *= 1.f / g_T[b];                       // fold softmax denominator
    float* dst;
    if (dsel == 0)      dst = g_Rlog + b * (HOPS * NR);
    else if (dsel == 1) dst = g_Clog + b * (HOPS * 2);
    else                dst = g_LD + b * H;
    atomicAdd(&dst[col], a);
}

// ---------------- f-pass device bodies ----------------
__device__ __forceinline__ float normFac(int b, int hop) {
    float Dd = g_sums[b * HOPS + 0] + 1e-6f;
    for (int h2 = 1; h2 <= hop; h2++) Dd = g_sums[b * HOPS + h2] + 1e-6f * Dd;
    return 1.f / Dd;
}

// sum(raw) + max(raw*sc) for chunk c of (b,hop); 256 threads
__device__ void f1_body(int c, int b, int hop) {
    int tid = threadIdx.x;
    int lane = tid & 31, wid = tid >> 5;
    __shared__ float redS[8], redM[8];
    int bh = b * HOPS + hop;
    const float* wr = g_walkraw + (size_t)bh * NE + c * 2500;
    const float* sc = g_scores + (size_t)b * NE + c * 2500;
    float s = 0.f, m = -1e30f;
    for (int e = tid; e < 2500; e += 256) {
        float w = wr[e];
        s += w;
        m = fmaxf(m, w * sc[e]);
    }
    s = warpSum(s);
    m = warpMax(m);
    if (lane == 0) { redS[wid] = s; redM[wid] = m; }
    __syncthreads();
    if (tid == 0) {
        float ss = 0.f, mm = redM[0];
        #pragma unroll
        for (int i = 0; i < 8; i++) { ss += redS[i]; mm = fmaxf(mm, redM[i]); }
        atomicAdd(&g_sums[bh], ss);
        atomicMaxF(&g_mx[bh], mm);
    }
}

// exp -> g_ebuf + esum for chunk c of (b,hop); 256 threads
__device__ void f2_body(int c, int b, int hop) {
    int tid = threadIdx.x;
    int lane = tid & 31, wid = tid >> 5;
    __shared__ float red[8];
    int bh = b * HOPS + hop;
    float fac = normFac(b, hop);
    float mx = g_mx[bh] * fac;
    const float* wr = g_walkraw + (size_t)bh * NE + c * 2500;
    const float* sc = g_scores + (size_t)b * NE + c * 2500;
    float* eb = g_ebuf + (size_t)bh * NE + c * 2500;
    float s = 0.f;
    for (int e = tid; e < 2500; e += 256) {
        float v = expf(wr[e] * fac * sc[e] - mx);
        eb[e] = v;
        s += v;
    }
    s = warpSum(s);
    if (lane == 0) red[wid] = s;
    __syncthreads();
    if (tid == 0) {
        float ss = 0.f;
        #pragma unroll
        for (int i = 0; i < 8; i++) ss += red[i];
        atomicAdd(&g_esum[bh], ss);
    }
}

// combine -> out for chunk c of (b,hop); checks softmax inline; 256 threads
__device__ void f3_body(int c, int b, int hop, float* __restrict__ out) {
    int tid = threadIdx.x;
    int bh = b * HOPS + hop;
    float fac = normFac(b, hop);
    float einv = 1.f / g_esum[bh];
    float l0 = g_Clog[bh * 2 + 0], l1 = g_Clog[bh * 2 + 1];
    float m2 = fmaxf(l0, l1);
    float e0 = expf(l0 - m2), e1 = expf(l1 - m2);
    float cinv = 1.f / (e0 + e1);
    float c0 = e0 * cinv;
    float c1 = e1 * cinv;
    const float* wr = g_walkraw + (size_t)bh * NE + c * 2500;
    const float* eb = g_ebuf + (size_t)bh * NE + c * 2500;
    float* o = out + (size_t)bh * NE + c * 2500;
    for (int e = tid; e < 2500; e += 256)
        o[e] = c0 * wr[e] * fac + c1 * eb[e] * einv;
}

// scatter body (unnormalized rels; Z cancels through walk normalization)
__device__ void scatter_body(int hop, int sb, const float* __restrict__ init_ent,
                             const int* __restrict__ heads, const int* __restrict__ rels,
                             const int* __restrict__ tails) {
    int idx = sb * 256 + threadIdx.x;   // < 800000
    int b = idx / NT;
    int h = heads[idx];
    int r = rels[idx];
    int t = tails[idx];
    float prev = (hop == 0) ? init_ent[b * NE + h]
                            : g_walkraw[(size_t)(b * HOPS + hop - 1) * NE + h];
    float trip = expf(g_Rlog[(b * HOPS + hop) * NR + r]) * prev;
    atomicAdd(&g_walkraw[(size_t)(b * HOPS + hop) * NE + t], trip);
}

// ---------------- fused launches ----------------

// hop-0 scatter + ALL scores, STRIPED 5:4 (measured-best ratio; 5625 blocks)
__global__ void k_sc0(const float* __restrict__ init_ent,
                      const int* __restrict__ heads, const int* __restrict__ rels,
                      const int* __restrict__ tails, const float* __restrict__ EE) {
    __shared__ float4 sLD[B * 192];
    int j = blockIdx.x % 9, g = blockIdx.x / 9;
    int tid = threadIdx.x;              // 256
    int lane = tid & 31, wid = tid >> 5;

    if (j < 5) {
        scatter_body(0, g * 5 + j, init_ent, heads, rels, tails);
    } else {
        const float4* LD4 = (const float4*)g_LD;
        for (int i = tid; i < B * 192; i += 256) sLD[i] = LD4[i];
        __syncthreads();
        int e = (g * 4 + (j - 5)) * 8 + wid;
        const float4* base = (const float4*)(EE + (size_t)e * 3072);
        float acc[B];
        #pragma unroll
        for (int b = 0; b < B; b++) acc[b] = 0.f;
        #pragma unroll
        for (int it = 0; it < 6; it++) {
            int jj = lane + it * 32;
            float4 v0 = base[jj], v1 = base[jj + 192], v2 = base[jj + 384], v3 = base[jj + 576];
            float4 sx;
            sx.x = v0.x + v1.x + v2.x + v3.x;
            sx.y = v0.y + v1.y + v2.y + v3.y;
            sx.z = v0.z + v1.z + v2.z + v3.z;
            sx.w = v0.w + v1.w + v2.w + v3.w;
            #pragma unroll
            for (int b = 0; b < B; b++) {
                float4 l = sLD[b * 192 + jj];
                acc[b] += sx.x * l.x + sx.y * l.y + sx.z * l.z + sx.w * l.w;
            }
        }
        #pragma unroll
        for (int b = 0; b < B; b++) {
            float v = warpSum(acc[b]);
            if (lane == 0) g_scores[b * NE + e] = v;
        }
    }
}

// scatter hop1 (plain, 3125 blocks)
__global__ void k_s1(const int* __restrict__ heads, const int* __restrict__ rels,
                     const int* __restrict__ tails) {
    scatter_body(1, blockIdx.x, nullptr, heads, rels, tails);
}

// scatter hop2 + f1(h0) + f1(h1) striped: groups of 51 (49 scatter + 2 f1),
// 64 groups = 3264 blocks. walkraw h0/h1 are final before this launch.
__global__ void k_s2f(const int* __restrict__ heads, const int* __restrict__ rels,
                      const int* __restrict__ tails) {
    int j = blockIdx.x % 51, g = blockIdx.x / 51;
    if (j < 49) {
        int sb = g * 49 + j;
        if (sb < 3125) scatter_body(2, sb, nullptr, heads, rels, tails);
    } else if (j == 49) {
        f1_body(g & 7, g >> 3, 0);
    } else {
        f1_body(g & 7, g >> 3, 1);
    }
}

// tail A: f1(h2) | f2(h0) | f2(h1) — 192 blocks
__global__ void k_fa() {
    int sec = blockIdx.x >> 6, g = blockIdx.x & 63;
    if (sec == 0)      f1_body(g & 7, g >> 3, 2);
    else if (sec == 1) f2_body(g & 7, g >> 3, 0);
    else               f2_body(g & 7, g >> 3, 1);
}

// tail B: f2(h2) | f3(h0) | f3(h1) — 192 blocks
__global__ void k_fb(float* __restrict__ out) {
    int sec = blockIdx.x >> 6, g = blockIdx.x & 63;
    if (sec == 0)      f2_body(g & 7, g >> 3, 2);
    else if (sec == 1) f3_body(g & 7, g >> 3, 0, out);
    else               f3_body(g & 7, g >> 3, 1, out);
}

// tail C: f3(h2) — 64 blocks
__global__ void k_fc(float* __restrict__ out) {
    int g = blockIdx.x;
    f3_body(g & 7, g >> 3, 2, out);
}

// ---------------- launcher ----------------
extern "C" void kernel_launch(void* const* d_in, const int* in_sizes, int n_in,
                              void* d_out, int out_size) {
    const float* lhs      = (const float*)d_in[0];
    const float* mask     = (const float*)d_in[1];
    const float* init_ent = (const float*)d_in[2];
    const float* EE       = (const float*)d_in[3];
    // d_in[4] = W_q  (eliminated: constant term cancels in pointer softmax)
    const float* Wv       = (const float*)d_in[5];
    const float* Wp       = (const float*)d_in[6];
    const float* Wr       = (const float*)d_in[7];
    const float* Wc       = (const float*)d_in[8];
    const float* Lw       = (const float*)d_in[9];
    const int*   heads    = (const int*)d_in[10];
    const int*   rels     = (const int*)d_in[11];
    const int*   tails    = (const int*)d_in[12];
    float* out = (float*)d_out;

    k_init  <<<1875, 256>>>(Wv, Wp);                        // 1
    { dim3 g(32, B); k_D <<<g, 192>>>(lhs, mask); }         // 2
    { dim3 g(12, 24, 8); k_lin <<<g, 128>>>(Wr, Wc, Lw); }  // 3
    k_sc0   <<<5625, 256>>>(init_ent, heads, rels, tails, EE); // 4 (profiled slot)
    k_s1    <<<3125, 256>>>(heads, rels, tails);            // 5
    k_s2f   <<<3264, 256>>>(heads, rels, tails);            // 6
    k_fa    <<<192, 256>>>();                               // 7
    k_fb    <<<192, 256>>>(out);                            // 8
    k_fc    <<<64, 256>>>(out);                             // 9
}